// round 1
// baseline (speedup 1.0000x reference)
#include <cuda_runtime.h>

#define T_STEPS 16384
#define H 361

#define SEG 48
#define SEGP 52
#define NSEG 8
#define HP (NSEG * SEGP)   /* 416 */
#define RPC 46
#define CSZ 8

#define KAPPA_F 32.84045313f
#define NORMF   2.2773755f   /* sqrt(K/(2pi)) / asymptotic-I0-series */
#define DEG2RAD 0.017453292519943295f

// ---------------- device scratch (static, no runtime allocation) ----------------
__device__ float g_xw[T_STEPS * H];     // precomputed input drive xw[t][j]
__device__ float g_W2T[H * 368];        // transposed angle weights: [g][j], stride 368
__device__ float g_A[H];                // rank-1 rule weight projection
__device__ float g_C[H];                // bias collapse
__device__ float g_hs[T_STEPS * H];     // hidden states

// ---------------- small PTX helpers ----------------
__device__ __forceinline__ unsigned smem_u32(const void* p) {
    return (unsigned)__cvta_generic_to_shared(p);
}
__device__ __forceinline__ unsigned mapa_u32(unsigned addr, unsigned rank) {
    unsigned r;
    asm("mapa.shared::cluster.u32 %0, %1, %2;" : "=r"(r) : "r"(addr), "r"(rank));
    return r;
}

// ---------------- K0: collapse rule projection + biases ----------------
__global__ void k0_prep(const float* __restrict__ w_rule, const float* __restrict__ b_rule,
                        const float* __restrict__ w_ih, const float* __restrict__ b_ih,
                        const float* __restrict__ b_hh) {
    int j = blockIdx.x * blockDim.x + threadIdx.x;
    if (j >= H) return;
    float a = 0.f, c = 0.f;
    const float* wr = w_ih + j * 489;
    for (int k = 0; k < 128; k++) {
        float w = wr[k];
        a = fmaf(w_rule[k], w, a);
        c = fmaf(b_rule[k], w, c);
    }
    g_A[j] = a;
    g_C[j] = c + b_ih[j] + b_hh[j];
}

// ---------------- K0b: transpose angle block of w_ih for coalesced reads ----------------
__global__ void k0_transpose(const float* __restrict__ w_ih) {
    int idx = blockIdx.x * blockDim.x + threadIdx.x;
    if (idx >= H * H) return;
    int j = idx / H;
    int g = idx - j * H;
    g_W2T[g * 368 + j] = w_ih[j * 489 + 128 + g];
}

// ---------------- K1: xw[t][j] = vonMises(t) . W2[:,j] + rule[t]*A[j] + C[j] ----------------
#define TT 16
__global__ __launch_bounds__(384) void k1_xw(const float* __restrict__ angle,
                                             const float* __restrict__ rule) {
    __shared__ float sE[TT][H];
    __shared__ float sAng[TT], sRule[TT];
    int tid = threadIdx.x;
    int t0 = blockIdx.x * TT;
    if (tid < TT) {
        sAng[tid]  = angle[t0 + tid] * DEG2RAD;
        sRule[tid] = rule[t0 + tid];
    }
    __syncthreads();
    if (tid < H) {
        float gr = (float)tid * DEG2RAD;
        #pragma unroll
        for (int tt = 0; tt < TT; tt++) {
            float th = gr - sAng[tt];
            sE[tt][tid] = __expf(KAPPA_F * (cosf(th) - 1.0f)) * NORMF;
        }
    }
    __syncthreads();
    if (tid < H) {
        float acc[TT];
        #pragma unroll
        for (int tt = 0; tt < TT; tt++) acc[tt] = 0.f;
        #pragma unroll 2
        for (int g = 0; g < H; g++) {
            float w = g_W2T[g * 368 + tid];
            #pragma unroll
            for (int tt = 0; tt < TT; tt++) acc[tt] = fmaf(sE[tt][g], w, acc[tt]);
        }
        float aj = g_A[tid], cj = g_C[tid];
        #pragma unroll
        for (int tt = 0; tt < TT; tt++)
            g_xw[(t0 + tt) * H + tid] = acc[tt] + fmaf(sRule[tt], aj, cj);
    }
}

// ---------------- K2: sequential RNN across an 8-CTA cluster ----------------
// CTA r owns output rows [r*46, r*46+46). Thread (rr, s) owns row r*46+rr,
// column segment [s*48, s*48+48) — weights live in registers for the whole kernel.
// Each step: dot (regs x smem-h) -> 3x shfl reduce over the 8 column segments ->
// tanh -> broadcast h slice to all 8 CTAs via st.shared::cluster -> mbarrier round.
__global__ void __cluster_dims__(CSZ, 1, 1) __launch_bounds__(384, 1)
k2_rnn(const float* __restrict__ w_hh) {
    __shared__ float hbuf0[HP];
    __shared__ float hbuf1[HP];
    __shared__ __align__(8) unsigned long long mbar;

    int tid = threadIdx.x;
    unsigned rank;
    asm("mov.u32 %0, %%cluster_ctarank;" : "=r"(rank));
    int s  = tid & 7;
    int rr = tid >> 3;
    int row = (int)rank * RPC + rr;
    bool active = (rr < RPC) && (row < H);
    bool leader = active && (s == 0);

    for (int i = tid; i < HP; i += 384) { hbuf0[i] = 0.f; hbuf1[i] = 0.f; }
    unsigned mb_local = smem_u32(&mbar);
    if (tid == 0) {
        unsigned cnt = H; // 361 arrivals expected per phase
        asm volatile("mbarrier.init.shared.b64 [%0], %1;" :: "r"(mb_local), "r"(cnt) : "memory");
    }

    // per-thread weight slice in registers (zeros for padding)
    float w[SEG];
    #pragma unroll
    for (int i = 0; i < SEG; i++) {
        int col = s * SEG + i;
        w[i] = (active && col < H) ? w_hh[row * H + col] : 0.f;
    }

    // precomputed DSMEM destinations for this thread's (row -> CTA s) broadcast
    int idx_store = (row / SEG) * SEGP + (row % SEG);
    unsigned dst0 = 0, dst1 = 0;
    if (active) {
        dst0 = mapa_u32(smem_u32(&hbuf0[idx_store]), (unsigned)s);
        dst1 = mapa_u32(smem_u32(&hbuf1[idx_store]), (unsigned)s);
    }
    unsigned arrive_addr = 0;
    unsigned my_rows = (rank == CSZ - 1) ? (unsigned)(H - RPC * (CSZ - 1)) : (unsigned)RPC;
    if (tid < CSZ) arrive_addr = mapa_u32(mb_local, (unsigned)tid);

    float xw_cur = 0.f;
    if (leader) xw_cur = g_xw[row];

    __syncthreads();
    asm volatile("barrier.cluster.arrive.aligned;" ::: "memory");
    asm volatile("barrier.cluster.wait.aligned;" ::: "memory");

    for (int t = 0; t < T_STEPS; t++) {
        const float* cur = (t & 1) ? hbuf1 : hbuf0;
        float xw_nxt = 0.f;
        if (leader && (t + 1 < T_STEPS)) xw_nxt = __ldg(&g_xw[(t + 1) * H + row]);

        const float4* h4 = reinterpret_cast<const float4*>(cur + s * SEGP);
        float a0 = 0.f, a1 = 0.f, a2 = 0.f, a3 = 0.f;
        #pragma unroll
        for (int i = 0; i < SEG / 4; i++) {
            float4 hv = h4[i];
            a0 = fmaf(w[4 * i + 0], hv.x, a0);
            a1 = fmaf(w[4 * i + 1], hv.y, a1);
            a2 = fmaf(w[4 * i + 2], hv.z, a2);
            a3 = fmaf(w[4 * i + 3], hv.w, a3);
        }
        float acc = (a0 + a1) + (a2 + a3);
        acc += __shfl_xor_sync(0xffffffffu, acc, 1);
        acc += __shfl_xor_sync(0xffffffffu, acc, 2);
        acc += __shfl_xor_sync(0xffffffffu, acc, 4);

        float hval = 0.f;
        if (leader) {
            hval = tanhf(acc + xw_cur);
            g_hs[t * H + row] = hval;
        }
        hval = __shfl_sync(0xffffffffu, hval, tid & 24);  // broadcast from s==0 lane of group

        if (active) {
            unsigned dst = (t & 1) ? dst0 : dst1;  // write h_{t+1} into buf[(t+1)&1]
            asm volatile("st.shared::cluster.f32 [%0], %1;" :: "r"(dst), "f"(hval) : "memory");
        }
        __syncthreads();
        if (tid < CSZ) {
            asm volatile("mbarrier.arrive.release.cluster.shared::cluster.b64 _, [%0], %1;"
                         :: "r"(arrive_addr), "r"(my_rows) : "memory");
        }
        {
            unsigned parity = (unsigned)(t & 1);
            asm volatile(
                "{\n\t.reg .pred P1;\n\t"
                "WAITLP_%=:\n\t"
                "mbarrier.try_wait.parity.acquire.cluster.shared::cta.b64 P1, [%0], %1, 0x989680;\n\t"
                "@!P1 bra WAITLP_%=;\n\t}"
                :: "r"(mb_local), "r"(parity) : "memory");
        }
        xw_cur = xw_nxt;
    }
    asm volatile("barrier.cluster.arrive.aligned;" ::: "memory");
    asm volatile("barrier.cluster.wait.aligned;" ::: "memory");
}

// ---------------- K3: outcome_pre + hs copy-out ----------------
__global__ void k3_outcome(const float* __restrict__ w_fc, const float* __restrict__ b_fc,
                           float* __restrict__ pre) {
    __shared__ float swfc[H];
    for (int i = threadIdx.x; i < H; i += blockDim.x) swfc[i] = w_fc[i];
    __syncthreads();
    int lane = threadIdx.x & 31;
    int wid  = threadIdx.x >> 5;
    int wpb  = blockDim.x >> 5;
    float bf = b_fc[0];
    for (int t = blockIdx.x * wpb + wid; t < T_STEPS; t += gridDim.x * wpb) {
        const float* hrow = g_hs + t * H;
        float acc = 0.f;
        for (int i = lane; i < H; i += 32) acc = fmaf(hrow[i], swfc[i], acc);
        #pragma unroll
        for (int o = 16; o > 0; o >>= 1) acc += __shfl_xor_sync(0xffffffffu, acc, o);
        if (lane == 0) pre[t] = acc + bf;
    }
}

__global__ void k3_copy(float* __restrict__ dst) {
    const float4* src = reinterpret_cast<const float4*>(g_hs);
    float4* d = reinterpret_cast<float4*>(dst);
    int n4 = T_STEPS * H / 4;
    for (int i = blockIdx.x * blockDim.x + threadIdx.x; i < n4; i += gridDim.x * blockDim.x)
        d[i] = src[i];
}

// ---------------- launch ----------------
extern "C" void kernel_launch(void* const* d_in, const int* in_sizes, int n_in,
                              void* d_out, int out_size) {
    const float* angle  = (const float*)d_in[0];
    const float* rule   = (const float*)d_in[1];
    const float* w_rule = (const float*)d_in[2];
    const float* b_rule = (const float*)d_in[3];
    const float* w_ih   = (const float*)d_in[4];
    const float* w_hh   = (const float*)d_in[5];
    const float* b_ih   = (const float*)d_in[6];
    const float* b_hh   = (const float*)d_in[7];
    const float* w_fc   = (const float*)d_in[8];
    const float* b_fc   = (const float*)d_in[9];
    float* out = (float*)d_out;

    k0_prep<<<(H + 255) / 256, 256>>>(w_rule, b_rule, w_ih, b_ih, b_hh);
    k0_transpose<<<(H * H + 255) / 256, 256>>>(w_ih);
    k1_xw<<<T_STEPS / TT, 384>>>(angle, rule);
    k2_rnn<<<CSZ, 384>>>(w_hh);

    // Output layout: reference returns (outcome_pre [1,T,1], out [1,T,361]).
    float* pre = nullptr;
    float* hs_dst = nullptr;
    if (out_size == T_STEPS * (H + 1)) { pre = out; hs_dst = out + T_STEPS; }
    else if (out_size == T_STEPS * H)  { hs_dst = out; }
    else if (out_size == T_STEPS)      { pre = out; }
    else {
        pre = out;
        if (out_size >= T_STEPS * (H + 1)) hs_dst = out + (out_size - T_STEPS * H);
    }
    if (hs_dst) k3_copy<<<1024, 256>>>(hs_dst);
    if (pre)    k3_outcome<<<256, 256>>>(w_fc, b_fc, pre);
}